// round 8
// baseline (speedup 1.0000x reference)
#include <cuda_runtime.h>
#include <math.h>

// SenseEmbedding:
//  x:   [16384, 12] int32   -- [w0, w1, ctx0..ctx9]
//  W_g: [100000, 128] f32
//  W_s: [100000, 8, 128] f32
//  out: [16384, 1] f32
//
// One warp per row, persistent grid (148 SMs x 4 blocks, one wave).
// W_g rows: LDG.128 gathers (coalesced 512B, L2-resident across replays).
// W_s sense blocks: each row needs one CONTIGUOUS 4KB chunk -> loaded with a
// single cp.async.bulk (UBLKCP) into a per-warp smem slot, evict-first L2
// hint, completion via per-warp mbarrier. This removes W_s from the LSU/L1
// path (8 LDG.128 -> 1 bulk op), frees ~32 regs, and overlaps the bulk copy
// with the 11 W_g gathers.

#define CTX 10
#define NUM_SENSES 8
#define VEC4 32   // 128 floats = 32 float4
#define WS_BYTES 4096

#define NBLOCKS 592   // 148 SMs * 4 blocks
#define NTHREADS 256  // 8 warps/block
#define WARPS_PER_BLOCK 8

__device__ __forceinline__ unsigned smem_addr(const void* p)
{
    unsigned a;
    asm("{ .reg .u64 t; cvta.to.shared.u64 t, %1; cvt.u32.u64 %0, t; }"
        : "=r"(a) : "l"(p));
    return a;
}

__global__ void __launch_bounds__(NTHREADS, 4)
sense_embedding_kernel(const int4* __restrict__ x4,
                       const float4* __restrict__ Wg,
                       const float4* __restrict__ Ws,
                       float* __restrict__ out,
                       int batch)
{
    __shared__ __align__(128) float4 sbuf[WARPS_PER_BLOCK][NUM_SENSES * VEC4]; // 8 x 4KB
    __shared__ __align__(8) unsigned long long mbar[WARPS_PER_BLOCK];

    int wid  = threadIdx.x >> 5;
    int lane = threadIdx.x & 31;

    unsigned bar = smem_addr(&mbar[wid]);
    unsigned buf = smem_addr(&sbuf[wid][0]);

    if (lane == 0)
        asm volatile("mbarrier.init.shared.b64 [%0], 1;" :: "r"(bar) : "memory");
    asm volatile("fence.proxy.async.shared::cta;" ::: "memory");
    __syncwarp();

    unsigned long long pol;   // evict-first for the one-shot W_s stream
    asm("createpolicy.fractional.L2::evict_first.b64 %0, 1.0;" : "=l"(pol));

    int warp0 = blockIdx.x * WARPS_PER_BLOCK + wid;
    const int warp_stride = NBLOCKS * WARPS_PER_BLOCK;   // 4736
    int phase = 0;

    for (int row = warp0; row < batch; row += warp_stride) {
        // all lanes must be done reading sbuf before the next overwrite
        __syncwarp();

        const int4* xr = x4 + (size_t)row * 3;
        int4 xa = __ldg(&xr[0]);
        int4 xb = __ldg(&xr[1]);
        int4 xc = __ldg(&xr[2]);
        int w0 = xa.x, w1 = xa.y;
        int toks[CTX] = { xa.z, xa.w, xb.x, xb.y, xb.z,
                          xb.w, xc.x, xc.y, xc.z, xc.w };

        // ---- kick off the 4KB W_s bulk copy (async, evict-first) ----
        if (lane == 0) {
            asm volatile("mbarrier.arrive.expect_tx.shared.b64 _, [%0], %1;"
                         :: "r"(bar), "r"(WS_BYTES) : "memory");
            const void* src = (const void*)(Ws + (size_t)w0 * (NUM_SENSES * VEC4));
            asm volatile(
                "cp.async.bulk.shared::cta.global.mbarrier::complete_tx::bytes"
                ".L2::cache_hint [%0], [%1], %2, [%3], %4;"
                :: "r"(buf), "l"(src), "r"(WS_BYTES), "r"(bar), "l"(pol)
                : "memory");
        }

        // ---- overlap: W_g gathers (target + 10 context rows) ----
        float4 tv = __ldg(&Wg[(size_t)w1 * VEC4 + lane]);

        float4 acc = make_float4(0.f, 0.f, 0.f, 0.f);
#pragma unroll
        for (int i = 0; i < CTX; i++) {
            float4 cv = __ldg(&Wg[(size_t)toks[i] * VEC4 + lane]);
            acc.x += cv.x; acc.y += cv.y; acc.z += cv.z; acc.w += cv.w;
        }

        // ---- wait for the sense block (acquire) ----
        {
            unsigned done;
            asm volatile(
                "{\n\t.reg .pred p;\n\t"
                "mbarrier.try_wait.parity.acquire.cta.shared::cta.b64 p, [%1], %2;\n\t"
                "selp.b32 %0, 1, 0, p;\n\t}"
                : "=r"(done) : "r"(bar), "r"(phase) : "memory");
            if (!done) {
                asm volatile(
                    "{\n\t.reg .pred P1;\n\t"
                    "W0_%=:\n\t"
                    "mbarrier.try_wait.parity.acquire.cta.shared::cta.b64 P1, [%0], %1, 0x989680;\n\t"
                    "@P1 bra.uni W1_%=;\n\t"
                    "bra.uni W0_%=;\n\t"
                    "W1_%=:\n\t}"
                    :: "r"(bar), "r"(phase) : "memory");
            }
            phase ^= 1;
        }

        // ---- per-lane partial dots from smem (conflict-free LDS.128) ----
        float partial[NUM_SENSES];
#pragma unroll
        for (int s = 0; s < NUM_SENSES; s++) {
            float4 v = sbuf[wid][s * VEC4 + lane];
            partial[s] = v.x * acc.x + v.y * acc.y + v.z * acc.z + v.w * acc.w;
        }

        // ---- warp-reduce each score; argmax (first max wins) ----
        float best = -INFINITY;
        int bestk = 0;
#pragma unroll
        for (int s = 0; s < NUM_SENSES; s++) {
            float p = partial[s];
            p += __shfl_xor_sync(0xffffffffu, p, 16);
            p += __shfl_xor_sync(0xffffffffu, p, 8);
            p += __shfl_xor_sync(0xffffffffu, p, 4);
            p += __shfl_xor_sync(0xffffffffu, p, 2);
            p += __shfl_xor_sync(0xffffffffu, p, 1);
            if (p > best) { best = p; bestk = s; }  // warp-uniform
        }

        // ---- chosen sense from smem + final dot ----
        float4 ch = sbuf[wid][bestk * VEC4 + lane];
        float d = ch.x * tv.x + ch.y * tv.y + ch.z * tv.z + ch.w * tv.w;
        d += __shfl_xor_sync(0xffffffffu, d, 16);
        d += __shfl_xor_sync(0xffffffffu, d, 8);
        d += __shfl_xor_sync(0xffffffffu, d, 4);
        d += __shfl_xor_sync(0xffffffffu, d, 2);
        d += __shfl_xor_sync(0xffffffffu, d, 1);

        if (lane == 0)
            out[row] = 1.0f / (1.0f + __expf(-d));
    }
}

extern "C" void kernel_launch(void* const* d_in, const int* in_sizes, int n_in,
                              void* d_out, int out_size)
{
    const int4*   x  = (const int4*)d_in[0];
    const float4* Wg = (const float4*)d_in[1];
    const float4* Ws = (const float4*)d_in[2];
    float* out = (float*)d_out;

    int batch = in_sizes[0] / (2 + CTX);   // 16384
    sense_embedding_kernel<<<NBLOCKS, NTHREADS>>>(x, Wg, Ws, out, batch);
}

// round 9
// speedup vs baseline: 1.0152x; 1.0152x over previous
#include <cuda_runtime.h>
#include <math.h>

// SenseEmbedding:
//  x:   [16384, 12] int32   -- [w0, w1, ctx0..ctx9]
//  W_g: [100000, 128] f32
//  W_s: [100000, 8, 128] f32
//  out: [16384, 1] f32
//
// Converged design: one warp per row (lane = float4 slice; every gather is a
// coalesced 512B access), persistent single-wave grid (148 SMs x 4 blocks).
//  - W_g gathers: __ldcg (L2-cached, L1 no-allocate -- L1 hit rate ~0, so
//    skip 92MB/pass of useless L1 fills).
//  - W_s sense blocks: __ldcs evict-first stream; protects W_g L2 residency
//    (measured 39.7 -> 16.9us vs default policy).
// Steady state is LTS-transit bound (~160MB compulsory bytes/pass); four
// structurally different implementations all measured 16.9-17.2us.

#define CTX 10
#define NUM_SENSES 8
#define VEC4 32   // 128 floats = 32 float4

#define NBLOCKS 592   // 148 SMs * 4 blocks, exactly one wave
#define NTHREADS 256  // 8 warps/block

__global__ void __launch_bounds__(NTHREADS, 4)
sense_embedding_kernel(const int4* __restrict__ x4,
                       const float4* __restrict__ Wg,
                       const float4* __restrict__ Ws,
                       float* __restrict__ out,
                       int batch)
{
    int warp0 = (blockIdx.x * NTHREADS + threadIdx.x) >> 5;
    int lane = threadIdx.x & 31;
    const int warp_stride = (NBLOCKS * NTHREADS) >> 5;   // 4736 warps

    for (int row = warp0; row < batch; row += warp_stride) {
        // x row = 12 ints = 3 x int4 (warp-uniform broadcast loads)
        const int4* xr = x4 + (size_t)row * 3;
        int4 xa = __ldg(&xr[0]);
        int4 xb = __ldg(&xr[1]);
        int4 xc = __ldg(&xr[2]);
        int w0 = xa.x, w1 = xa.y;
        int toks[CTX] = { xa.z, xa.w, xb.x, xb.y, xb.z,
                          xb.w, xc.x, xc.y, xc.z, xc.w };

        // ---- independent gathers: target + 8 senses + 10 context rows ----
        float4 tv = __ldcg(&Wg[(size_t)w1 * VEC4 + lane]);   // target row

        const float4* ws_row = Ws + (size_t)w0 * (NUM_SENSES * VEC4) + lane;
        float4 v[NUM_SENSES];
#pragma unroll
        for (int s = 0; s < NUM_SENSES; s++)
            v[s] = __ldcs(&ws_row[s * VEC4]);                // evict-first

        float4 acc = make_float4(0.f, 0.f, 0.f, 0.f);
#pragma unroll
        for (int i = 0; i < CTX; i++) {
            float4 cv = __ldcg(&Wg[(size_t)toks[i] * VEC4 + lane]);
            acc.x += cv.x; acc.y += cv.y; acc.z += cv.z; acc.w += cv.w;
        }

        // ---- per-lane partial dots ----
        float partial[NUM_SENSES];
#pragma unroll
        for (int s = 0; s < NUM_SENSES; s++)
            partial[s] = v[s].x * acc.x + v[s].y * acc.y
                       + v[s].z * acc.z + v[s].w * acc.w;

        // ---- warp-reduce each score; argmax (first max wins, jnp.argmax);
        //      track the chosen per-lane dot-with-target alongside ----
        float best = -INFINITY;
        float dbest = 0.f;
#pragma unroll
        for (int s = 0; s < NUM_SENSES; s++) {
            float p = partial[s];
            p += __shfl_xor_sync(0xffffffffu, p, 16);
            p += __shfl_xor_sync(0xffffffffu, p, 8);
            p += __shfl_xor_sync(0xffffffffu, p, 4);
            p += __shfl_xor_sync(0xffffffffu, p, 2);
            p += __shfl_xor_sync(0xffffffffu, p, 1);
            if (p > best) {            // warp-uniform decision
                best = p;
                dbest = v[s].x * tv.x + v[s].y * tv.y
                      + v[s].z * tv.z + v[s].w * tv.w;
            }
        }

        // ---- reduce the chosen dot, sigmoid, store ----
        float d = dbest;
        d += __shfl_xor_sync(0xffffffffu, d, 16);
        d += __shfl_xor_sync(0xffffffffu, d, 8);
        d += __shfl_xor_sync(0xffffffffu, d, 4);
        d += __shfl_xor_sync(0xffffffffu, d, 2);
        d += __shfl_xor_sync(0xffffffffu, d, 1);

        if (lane == 0)
            out[row] = 1.0f / (1.0f + __expf(-d));
    }
}

extern "C" void kernel_launch(void* const* d_in, const int* in_sizes, int n_in,
                              void* d_out, int out_size)
{
    const int4*   x  = (const int4*)d_in[0];
    const float4* Wg = (const float4*)d_in[1];
    const float4* Ws = (const float4*)d_in[2];
    float* out = (float*)d_out;

    int batch = in_sizes[0] / (2 + CTX);   // 16384
    sense_embedding_kernel<<<NBLOCKS, NTHREADS>>>(x, Wg, Ws, out, batch);
}